// round 2
// baseline (speedup 1.0000x reference)
#include <cuda_runtime.h>
#include <math.h>

#define B_  4
#define S_  1024
#define D_  1024
#define H_  16
#define DH_ 64
#define M_  (B_*S_)          // 4096 rows
#define EPS_ 1e-5f

// ---------------- scratch (no allocations allowed) ----------------
__device__ __align__(16) float g_h0[M_ * D_];     // GEMM output pre-BN (16.78 MB)
__device__ __align__(16) float g_mu[D_];
__device__ __align__(16) float g_rstd[D_];

// =================================================================
// Kernel 1: h0[m,n] = scale[n] * sum_k x[m,k] * W[n,k]
// Tiled fp32 GEMM: BM=BN=64, BK=16, 256 threads, 4x4 register tile.
// =================================================================
#define BM 64
#define BN 64
#define BK 16

__global__ __launch_bounds__(256) void gemm_k(const float* __restrict__ x,
                                              const float* __restrict__ W,
                                              const float* __restrict__ scale)
{
    __shared__ float As[BK][BM];
    __shared__ float Bs[BK][BN];

    const int m0  = blockIdx.y * BM;
    const int n0  = blockIdx.x * BN;
    const int tid = threadIdx.x;
    const int lrow = tid >> 2;          // 0..63
    const int lk   = (tid & 3) << 2;    // 0,4,8,12
    const int tx = tid & 15;            // 0..15 -> 4 output cols
    const int ty = tid >> 4;            // 0..15 -> 4 output rows

    float acc[4][4];
#pragma unroll
    for (int i = 0; i < 4; i++)
#pragma unroll
        for (int j = 0; j < 4; j++) acc[i][j] = 0.f;

    const float* xg = x + (size_t)(m0 + lrow) * D_;
    const float* wg = W + (size_t)(n0 + lrow) * D_;

    for (int k0 = 0; k0 < D_; k0 += BK) {
        float4 a = *(const float4*)(xg + k0 + lk);
        float4 b = *(const float4*)(wg + k0 + lk);
        __syncthreads();   // previous iteration's compute done before overwrite
        As[lk + 0][lrow] = a.x; As[lk + 1][lrow] = a.y;
        As[lk + 2][lrow] = a.z; As[lk + 3][lrow] = a.w;
        Bs[lk + 0][lrow] = b.x; Bs[lk + 1][lrow] = b.y;
        Bs[lk + 2][lrow] = b.z; Bs[lk + 3][lrow] = b.w;
        __syncthreads();
#pragma unroll
        for (int k = 0; k < BK; k++) {
            float4 av = *(const float4*)&As[k][ty << 2];
            float4 bv = *(const float4*)&Bs[k][tx << 2];
            acc[0][0] += av.x * bv.x; acc[0][1] += av.x * bv.y;
            acc[0][2] += av.x * bv.z; acc[0][3] += av.x * bv.w;
            acc[1][0] += av.y * bv.x; acc[1][1] += av.y * bv.y;
            acc[1][2] += av.y * bv.z; acc[1][3] += av.y * bv.w;
            acc[2][0] += av.z * bv.x; acc[2][1] += av.z * bv.y;
            acc[2][2] += av.z * bv.z; acc[2][3] += av.z * bv.w;
            acc[3][0] += av.w * bv.x; acc[3][1] += av.w * bv.y;
            acc[3][2] += av.w * bv.z; acc[3][3] += av.w * bv.w;
        }
    }

    const int nc = n0 + (tx << 2);
    float4 sc = *(const float4*)(scale + nc);
#pragma unroll
    for (int i = 0; i < 4; i++) {
        const int row = m0 + (ty << 2) + i;
        float4 o;
        o.x = acc[i][0] * sc.x; o.y = acc[i][1] * sc.y;
        o.z = acc[i][2] * sc.z; o.w = acc[i][3] * sc.w;
        *(float4*)&g_h0[(size_t)row * D_ + nc] = o;
    }
}

// =================================================================
// Kernel 2: per-feature mean / rstd over all 4096 (b,s) samples
// One block per feature, deterministic tree reduction.
// =================================================================
__global__ __launch_bounds__(256) void stats_k()
{
    const int f = blockIdx.x;
    const int tid = threadIdx.x;
    float s = 0.f, s2 = 0.f;
    for (int r = tid; r < M_; r += 256) {
        float v = g_h0[(size_t)r * D_ + f];
        s += v; s2 += v * v;
    }
#pragma unroll
    for (int off = 16; off > 0; off >>= 1) {
        s  += __shfl_down_sync(0xffffffffu, s,  off);
        s2 += __shfl_down_sync(0xffffffffu, s2, off);
    }
    __shared__ float ws[8], ws2[8];
    if ((tid & 31) == 0) { ws[tid >> 5] = s; ws2[tid >> 5] = s2; }
    __syncthreads();
    if (tid == 0) {
        float S = 0.f, S2 = 0.f;
#pragma unroll
        for (int i = 0; i < 8; i++) { S += ws[i]; S2 += ws2[i]; }
        float mu  = S / (float)M_;
        float var = S2 / (float)M_ - mu * mu;
        g_mu[f]   = mu;
        g_rstd[f] = rsqrtf(var + EPS_);
    }
}

// =================================================================
// Kernel 3: h = relu(gamma*(h0-mu)*rstd + beta) * mask
//             + residual + attention + positional        -> d_out
// =================================================================
__global__ __launch_bounds__(256) void apply_k(const float* __restrict__ gamma,
                                               const float* __restrict__ beta,
                                               const float* __restrict__ mask,
                                               const float* __restrict__ residual,
                                               const float* __restrict__ attention,
                                               const float* __restrict__ positional,
                                               float* __restrict__ out)
{
    const int n4 = (M_ * D_) / 4;
    for (int i = blockIdx.x * blockDim.x + threadIdx.x; i < n4;
         i += gridDim.x * blockDim.x) {
        const int f4 = i & (D_ / 4 - 1);
        float4 hv = ((const float4*)g_h0)[i];
        float4 g  = ((const float4*)gamma)[f4];
        float4 bt = ((const float4*)beta)[f4];
        float4 mu = ((const float4*)g_mu)[f4];
        float4 rs = ((const float4*)g_rstd)[f4];
        float4 mk = ((const float4*)mask)[i];
        float4 rd = ((const float4*)residual)[i];
        float4 at = ((const float4*)attention)[i];
        float4 ps = ((const float4*)positional)[i];
        float4 y;
        y.x = fmaxf(g.x * (hv.x - mu.x) * rs.x + bt.x, 0.f) * mk.x + rd.x + at.x + ps.x;
        y.y = fmaxf(g.y * (hv.y - mu.y) * rs.y + bt.y, 0.f) * mk.y + rd.y + at.y + ps.y;
        y.z = fmaxf(g.z * (hv.z - mu.z) * rs.z + bt.z, 0.f) * mk.z + rd.z + at.z + ps.z;
        y.w = fmaxf(g.w * (hv.w - mu.w) * rs.w + bt.w, 0.f) * mk.w + rd.w + at.w + ps.w;
        ((float4*)out)[i] = y;
    }
}

// =================================================================
// Kernel 4 (x6): one MHA stage, flash-attention style.
//   h_new[row] = h[row] + softmax((h+qb)·kbᵀ / 8) · vb    (per head)
// One thread owns one query row (QT=128 queries/block, one (b,head)
// per block). K/V tiles of 32 keys staged in smem as float4; scores
// processed in two KT/2=16 half-passes to cap register pressure.
// In-place h update is safe: K/V come only from inputs; each h row is
// read and written by exactly one thread.
// =================================================================
#define QT 128
#define KT 32
#define KH 16   // half-tile for score buffering

__global__ __launch_bounds__(128, 2) void flash_k(float* __restrict__ h,
                                                  const float* __restrict__ qb,
                                                  const float* __restrict__ kb,
                                                  const float* __restrict__ vb)
{
    __shared__ float4 Ks[KT][DH_ / 4];
    __shared__ float4 Vs[KT][DH_ / 4];

    const int tid = threadIdx.x;
    const int sq  = blockIdx.x * QT + tid;     // query position
    const int hh  = blockIdx.y;                // head
    const int b   = blockIdx.z;                // batch
    const size_t rowoff  = ((size_t)(b * S_ + sq)) * D_ + hh * DH_;
    const size_t headoff = ((size_t)b * S_) * D_ + hh * DH_;

    float4 q[16], o[16];
    {
        const float4* hrow = (const float4*)(h + rowoff);
        const float4* qrow = (const float4*)(qb + rowoff);
#pragma unroll
        for (int i = 0; i < 16; i++) {
            float4 a = hrow[i], c = qrow[i];
            q[i] = make_float4(a.x + c.x, a.y + c.y, a.z + c.z, a.w + c.w);
            o[i] = make_float4(0.f, 0.f, 0.f, 0.f);
        }
    }
    float m = -1e30f, l = 0.f;

    for (int kt = 0; kt < S_; kt += KT) {
        __syncthreads();
#pragma unroll
        for (int li = 0; li < 4; li++) {
            int idx = tid + li * 128;
            int j = idx >> 4, d4 = idx & 15;
            size_t go = headoff + (size_t)(kt + j) * D_ + d4 * 4;
            Ks[j][d4] = *(const float4*)(kb + go);
            Vs[j][d4] = *(const float4*)(vb + go);
        }
        __syncthreads();

        // two half-passes of KH keys each; same online-softmax stream
#pragma unroll
        for (int half = 0; half < 2; half++) {
            const int jb = half * KH;
            float p[KH];
            float mnew = m;
#pragma unroll
            for (int j = 0; j < KH; j++) {
                float s = 0.f;
#pragma unroll
                for (int d = 0; d < 16; d++) {
                    float4 kk = Ks[jb + j][d];
                    s += q[d].x * kk.x + q[d].y * kk.y + q[d].z * kk.z + q[d].w * kk.w;
                }
                s *= 0.125f;                   // 1/sqrt(64)
                p[j] = s;
                mnew = fmaxf(mnew, s);
            }
            float corr = __expf(m - mnew);
            m = mnew;
            l *= corr;
#pragma unroll
            for (int d = 0; d < 16; d++) {
                o[d].x *= corr; o[d].y *= corr; o[d].z *= corr; o[d].w *= corr;
            }
#pragma unroll
            for (int j = 0; j < KH; j++) {
                float pj = __expf(p[j] - m);
                l += pj;
#pragma unroll
                for (int d = 0; d < 16; d++) {
                    float4 vv = Vs[jb + j][d];
                    o[d].x += pj * vv.x; o[d].y += pj * vv.y;
                    o[d].z += pj * vv.z; o[d].w += pj * vv.w;
                }
            }
        }
    }

    const float inv = 1.f / l;
    float4* hw = (float4*)(h + rowoff);
#pragma unroll
    for (int i = 0; i < 16; i++) {
        float4 a = hw[i];
        a.x += o[i].x * inv; a.y += o[i].y * inv;
        a.z += o[i].z * inv; a.w += o[i].w * inv;
        hw[i] = a;
    }
}

// =================================================================
// launch
// =================================================================
extern "C" void kernel_launch(void* const* d_in, const int* in_sizes, int n_in,
                              void* d_out, int out_size)
{
    const float* x          = (const float*)d_in[0];
    const float* W          = (const float*)d_in[1];
    const float* scale      = (const float*)d_in[2];
    const float* gamma      = (const float*)d_in[3];
    const float* beta       = (const float*)d_in[4];
    const float* mask       = (const float*)d_in[5];
    const float* residual   = (const float*)d_in[6];
    const float* attention  = (const float*)d_in[7];
    const float* positional = (const float*)d_in[8];
    float* out = (float*)d_out;

    dim3 gg(D_ / BN, M_ / BM);              // (16, 64)
    gemm_k<<<gg, 256>>>(x, W, scale);

    stats_k<<<D_, 256>>>();

    apply_k<<<2048, 256>>>(gamma, beta, mask, residual, attention, positional, out);

    dim3 fg(S_ / QT, H_, B_);               // (8, 16, 4)
    for (int t = 0; t < 6; t++) {
        flash_k<<<fg, 128>>>(out,
                             (const float*)d_in[9  + 3 * t],
                             (const float*)d_in[10 + 3 * t],
                             (const float*)d_in[11 + 3 * t]);
    }
}

// round 5
// speedup vs baseline: 1.1353x; 1.1353x over previous
#include <cuda_runtime.h>
#include <math.h>

#define B_  4
#define S_  1024
#define D_  1024
#define H_  16
#define DH_ 64
#define M_  (B_*S_)          // 4096 rows
#define EPS_ 1e-5f

typedef unsigned long long ull;

// ---------------- scratch (no allocations allowed) ----------------
__device__ __align__(16) float g_h0[M_ * D_];     // GEMM output pre-BN
__device__ __align__(16) float g_mu[D_];
__device__ __align__(16) float g_rstd[D_];

// ---------------- packed f32x2 helpers (Blackwell FFMA2 path) -----
__device__ __forceinline__ ull d_fma2(ull a, ull b, ull c) {
    ull d;
    asm("fma.rn.f32x2 %0, %1, %2, %3;" : "=l"(d) : "l"(a), "l"(b), "l"(c));
    return d;
}
__device__ __forceinline__ ull d_add2(ull a, ull b) {
    ull d;
    asm("add.rn.f32x2 %0, %1, %2;" : "=l"(d) : "l"(a), "l"(b));
    return d;
}
__device__ __forceinline__ ull d_mul2(ull a, ull b) {
    ull d;
    asm("mul.rn.f32x2 %0, %1, %2;" : "=l"(d) : "l"(a), "l"(b));
    return d;
}
__device__ __forceinline__ ull pack2(float x, float y) {
    ull d;
    asm("mov.b64 %0, {%1, %2};" : "=l"(d) : "f"(x), "f"(y));
    return d;
}
__device__ __forceinline__ float2 unpack2(ull v) {
    float2 r;
    asm("mov.b64 {%0, %1}, %2;" : "=f"(r.x), "=f"(r.y) : "l"(v));
    return r;
}
__device__ __forceinline__ void cp16(unsigned int sdst, const void* gsrc) {
    asm volatile("cp.async.cg.shared.global [%0], [%1], 16;"
                 :: "r"(sdst), "l"(gsrc));
}

union F4U2 { float4 f; ulonglong2 u; };

// =================================================================
// Kernel 1: h0[m,n] = scale[n] * sum_k x[m,k] * W[n,k]
// =================================================================
#define BM 64
#define BN 64
#define BK 16

__global__ __launch_bounds__(256) void gemm_k(const float* __restrict__ x,
                                              const float* __restrict__ W,
                                              const float* __restrict__ scale)
{
    __shared__ float As[BK][BM];
    __shared__ float Bs[BK][BN];

    const int m0  = blockIdx.y * BM;
    const int n0  = blockIdx.x * BN;
    const int tid = threadIdx.x;
    const int lrow = tid >> 2;
    const int lk   = (tid & 3) << 2;
    const int tx = tid & 15;
    const int ty = tid >> 4;

    float acc[4][4];
#pragma unroll
    for (int i = 0; i < 4; i++)
#pragma unroll
        for (int j = 0; j < 4; j++) acc[i][j] = 0.f;

    const float* xg = x + (size_t)(m0 + lrow) * D_;
    const float* wg = W + (size_t)(n0 + lrow) * D_;

    for (int k0 = 0; k0 < D_; k0 += BK) {
        float4 a = *(const float4*)(xg + k0 + lk);
        float4 b = *(const float4*)(wg + k0 + lk);
        __syncthreads();
        As[lk + 0][lrow] = a.x; As[lk + 1][lrow] = a.y;
        As[lk + 2][lrow] = a.z; As[lk + 3][lrow] = a.w;
        Bs[lk + 0][lrow] = b.x; Bs[lk + 1][lrow] = b.y;
        Bs[lk + 2][lrow] = b.z; Bs[lk + 3][lrow] = b.w;
        __syncthreads();
#pragma unroll
        for (int k = 0; k < BK; k++) {
            float4 av = *(const float4*)&As[k][ty << 2];
            float4 bv = *(const float4*)&Bs[k][tx << 2];
            acc[0][0] += av.x * bv.x; acc[0][1] += av.x * bv.y;
            acc[0][2] += av.x * bv.z; acc[0][3] += av.x * bv.w;
            acc[1][0] += av.y * bv.x; acc[1][1] += av.y * bv.y;
            acc[1][2] += av.y * bv.z; acc[1][3] += av.y * bv.w;
            acc[2][0] += av.z * bv.x; acc[2][1] += av.z * bv.y;
            acc[2][2] += av.z * bv.z; acc[2][3] += av.z * bv.w;
            acc[3][0] += av.w * bv.x; acc[3][1] += av.w * bv.y;
            acc[3][2] += av.w * bv.z; acc[3][3] += av.w * bv.w;
        }
    }

    const int nc = n0 + (tx << 2);
    float4 sc = *(const float4*)(scale + nc);
#pragma unroll
    for (int i = 0; i < 4; i++) {
        const int row = m0 + (ty << 2) + i;
        float4 o;
        o.x = acc[i][0] * sc.x; o.y = acc[i][1] * sc.y;
        o.z = acc[i][2] * sc.z; o.w = acc[i][3] * sc.w;
        *(float4*)&g_h0[(size_t)row * D_ + nc] = o;
    }
}

// =================================================================
// Kernel 2: per-feature mean / rstd
// =================================================================
__global__ __launch_bounds__(256) void stats_k()
{
    const int f = blockIdx.x;
    const int tid = threadIdx.x;
    float s = 0.f, s2 = 0.f;
    for (int r = tid; r < M_; r += 256) {
        float v = g_h0[(size_t)r * D_ + f];
        s += v; s2 += v * v;
    }
#pragma unroll
    for (int off = 16; off > 0; off >>= 1) {
        s  += __shfl_down_sync(0xffffffffu, s,  off);
        s2 += __shfl_down_sync(0xffffffffu, s2, off);
    }
    __shared__ float ws[8], ws2[8];
    if ((tid & 31) == 0) { ws[tid >> 5] = s; ws2[tid >> 5] = s2; }
    __syncthreads();
    if (tid == 0) {
        float S = 0.f, S2 = 0.f;
#pragma unroll
        for (int i = 0; i < 8; i++) { S += ws[i]; S2 += ws2[i]; }
        float mu  = S / (float)M_;
        float var = S2 / (float)M_ - mu * mu;
        g_mu[f]   = mu;
        g_rstd[f] = rsqrtf(var + EPS_);
    }
}

// =================================================================
// Kernel 3: BN affine + ReLU*mask + residual/attn/pos adds -> d_out
// =================================================================
__global__ __launch_bounds__(256) void apply_k(const float* __restrict__ gamma,
                                               const float* __restrict__ beta,
                                               const float* __restrict__ mask,
                                               const float* __restrict__ residual,
                                               const float* __restrict__ attention,
                                               const float* __restrict__ positional,
                                               float* __restrict__ out)
{
    const int n4 = (M_ * D_) / 4;
    for (int i = blockIdx.x * blockDim.x + threadIdx.x; i < n4;
         i += gridDim.x * blockDim.x) {
        const int f4 = i & (D_ / 4 - 1);
        float4 hv = ((const float4*)g_h0)[i];
        float4 g  = ((const float4*)gamma)[f4];
        float4 bt = ((const float4*)beta)[f4];
        float4 mu = ((const float4*)g_mu)[f4];
        float4 rs = ((const float4*)g_rstd)[f4];
        float4 mk = ((const float4*)mask)[i];
        float4 rd = ((const float4*)residual)[i];
        float4 at = ((const float4*)attention)[i];
        float4 ps = ((const float4*)positional)[i];
        float4 y;
        y.x = fmaxf(g.x * (hv.x - mu.x) * rs.x + bt.x, 0.f) * mk.x + rd.x + at.x + ps.x;
        y.y = fmaxf(g.y * (hv.y - mu.y) * rs.y + bt.y, 0.f) * mk.y + rd.y + at.y + ps.y;
        y.z = fmaxf(g.z * (hv.z - mu.z) * rs.z + bt.z, 0.f) * mk.z + rd.z + at.z + ps.z;
        y.w = fmaxf(g.w * (hv.w - mu.w) * rs.w + bt.w, 0.f) * mk.w + rd.w + at.w + ps.w;
        ((float4*)out)[i] = y;
    }
}

// =================================================================
// Kernel 4 (x6): flash-attention stage, packed f32x2 math,
// cp.async double-buffered K/V tiles.
// One thread owns one query row. In-place h update is race-free
// (each row touched by exactly one thread; K/V from inputs only).
// =================================================================
#define QT 128
#define KT 32
#define KH 16

__global__ __launch_bounds__(128, 2) void flash_k(float* __restrict__ h,
                                                  const float* __restrict__ qb,
                                                  const float* __restrict__ kb,
                                                  const float* __restrict__ vb)
{
    // [buf][K=0/V=1][key][d4]
    __shared__ F4U2 KVs[2][2][KT][DH_ / 4];

    const int tid = threadIdx.x;
    const int sq  = blockIdx.x * QT + tid;
    const int hh  = blockIdx.y;
    const int b   = blockIdx.z;
    const size_t rowoff  = ((size_t)(b * S_ + sq)) * D_ + hh * DH_;
    const size_t headoff = ((size_t)b * S_) * D_ + hh * DH_;

    // q, o as packed f32x2 (32 u64 each)
    ull q2[32], o2[32];
    {
        const F4U2* hrow = (const F4U2*)(h + rowoff);
        const F4U2* qrow = (const F4U2*)(qb + rowoff);
#pragma unroll
        for (int i = 0; i < 16; i++) {
            F4U2 a = hrow[i], c = qrow[i];
            q2[2 * i]     = d_add2(a.u.x, c.u.x);
            q2[2 * i + 1] = d_add2(a.u.y, c.u.y);
            o2[2 * i]     = 0ull;
            o2[2 * i + 1] = 0ull;
        }
    }
    float m = -1e30f, l = 0.f;

    // tile loader: 8 x 16B cp.async per thread (K and V)
    auto load_tile = [&](int kt, int bf) {
#pragma unroll
        for (int li = 0; li < 4; li++) {
            int idx = tid + li * 128;
            int j = idx >> 4, d4 = idx & 15;
            const float* gk = kb + headoff + (size_t)(kt + j) * D_ + d4 * 4;
            const float* gv = vb + headoff + (size_t)(kt + j) * D_ + d4 * 4;
            cp16((unsigned int)__cvta_generic_to_shared(&KVs[bf][0][j][d4]), gk);
            cp16((unsigned int)__cvta_generic_to_shared(&KVs[bf][1][j][d4]), gv);
        }
        asm volatile("cp.async.commit_group;" ::: "memory");
    };

    load_tile(0, 0);

    for (int kt = 0, t = 0; kt < S_; kt += KT, t++) {
        asm volatile("cp.async.wait_group 0;" ::: "memory");
        __syncthreads();                 // tile t ready; everyone done with t-1
        if (kt + KT < S_) load_tile(kt + KT, (t + 1) & 1);
        const int bf = t & 1;
        const F4U2 (*Ks)[DH_ / 4] = KVs[bf][0];
        const F4U2 (*Vs)[DH_ / 4] = KVs[bf][1];

#pragma unroll
        for (int half = 0; half < 2; half++) {
            const int jb = half * KH;
            float p[KH];
            float mnew = m;
#pragma unroll 4
            for (int j = 0; j < KH; j++) {
                ull a0 = 0ull, a1 = 0ull, a2 = 0ull, a3 = 0ull;
                const F4U2* kr = Ks[jb + j];
#pragma unroll
                for (int d = 0; d < 16; d += 2) {
                    F4U2 k0 = kr[d], k1 = kr[d + 1];
                    a0 = d_fma2(q2[2 * d],     k0.u.x, a0);
                    a1 = d_fma2(q2[2 * d + 1], k0.u.y, a1);
                    a2 = d_fma2(q2[2 * d + 2], k1.u.x, a2);
                    a3 = d_fma2(q2[2 * d + 3], k1.u.y, a3);
                }
                a0 = d_add2(a0, a2);
                a1 = d_add2(a1, a3);
                a0 = d_add2(a0, a1);
                float2 sf = unpack2(a0);
                float s = (sf.x + sf.y) * 0.125f;   // 1/sqrt(64)
                p[j] = s;
                mnew = fmaxf(mnew, s);
            }
            float corr = __expf(m - mnew);
            m = mnew;
            l *= corr;
            {
                ull cc = pack2(corr, corr);
#pragma unroll
                for (int i = 0; i < 32; i++) o2[i] = d_mul2(o2[i], cc);
            }
#pragma unroll 4
            for (int j = 0; j < KH; j++) {
                float pj = __expf(p[j] - m);
                l += pj;
                ull pp = pack2(pj, pj);
                const F4U2* vr = Vs[jb + j];
#pragma unroll
                for (int d = 0; d < 16; d++) {
                    F4U2 vv = vr[d];
                    o2[2 * d]     = d_fma2(pp, vv.u.x, o2[2 * d]);
                    o2[2 * d + 1] = d_fma2(pp, vv.u.y, o2[2 * d + 1]);
                }
            }
        }
    }

    const float inv = 1.f / l;
    F4U2* hw = (F4U2*)(h + rowoff);
#pragma unroll
    for (int i = 0; i < 16; i++) {
        F4U2 a = hw[i];
        float2 e0 = unpack2(o2[2 * i]);
        float2 e1 = unpack2(o2[2 * i + 1]);
        a.f.x += e0.x * inv; a.f.y += e0.y * inv;
        a.f.z += e1.x * inv; a.f.w += e1.y * inv;
        hw[i] = a;
    }
}

// =================================================================
// launch
// =================================================================
extern "C" void kernel_launch(void* const* d_in, const int* in_sizes, int n_in,
                              void* d_out, int out_size)
{
    const float* x          = (const float*)d_in[0];
    const float* W          = (const float*)d_in[1];
    const float* scale      = (const float*)d_in[2];
    const float* gamma      = (const float*)d_in[3];
    const float* beta       = (const float*)d_in[4];
    const float* mask       = (const float*)d_in[5];
    const float* residual   = (const float*)d_in[6];
    const float* attention  = (const float*)d_in[7];
    const float* positional = (const float*)d_in[8];
    float* out = (float*)d_out;

    dim3 gg(D_ / BN, M_ / BM);
    gemm_k<<<gg, 256>>>(x, W, scale);

    stats_k<<<D_, 256>>>();

    apply_k<<<2048, 256>>>(gamma, beta, mask, residual, attention, positional, out);

    dim3 fg(S_ / QT, H_, B_);
    for (int t = 0; t < 6; t++) {
        flash_k<<<fg, 128>>>(out,
                             (const float*)d_in[9  + 3 * t],
                             (const float*)d_in[10 + 3 * t],
                             (const float*)d_in[11 + 3 * t]);
    }
}

// round 11
// speedup vs baseline: 1.2278x; 1.0815x over previous
#include <cuda_runtime.h>
#include <math.h>

#define B_  4
#define S_  1024
#define D_  1024
#define H_  16
#define DH_ 64
#define M_  (B_*S_)
#define EPS_ 1e-5f

typedef unsigned long long ull;

// ---------------- scratch (no allocations allowed) ----------------
__device__ __align__(16) float g_h0[M_ * D_];
__device__ __align__(16) float g_mu[D_];
__device__ __align__(16) float g_rstd[D_];

// ---------------- packed f32x2 helpers ----------------------------
__device__ __forceinline__ ull d_fma2(ull a, ull b, ull c) {
    ull d;
    asm("fma.rn.f32x2 %0, %1, %2, %3;" : "=l"(d) : "l"(a), "l"(b), "l"(c));
    return d;
}
__device__ __forceinline__ ull d_add2(ull a, ull b) {
    ull d;
    asm("add.rn.f32x2 %0, %1, %2;" : "=l"(d) : "l"(a), "l"(b));
    return d;
}
__device__ __forceinline__ ull d_mul2(ull a, ull b) {
    ull d;
    asm("mul.rn.f32x2 %0, %1, %2;" : "=l"(d) : "l"(a), "l"(b));
    return d;
}
__device__ __forceinline__ ull pack2(float x, float y) {
    ull d;
    asm("mov.b64 %0, {%1, %2};" : "=l"(d) : "f"(x), "f"(y));
    return d;
}
__device__ __forceinline__ float2 unpack2(ull v) {
    float2 r;
    asm("mov.b64 {%0, %1}, %2;" : "=f"(r.x), "=f"(r.y) : "l"(v));
    return r;
}
__device__ __forceinline__ void cp16(unsigned int sdst, const void* gsrc) {
    asm volatile("cp.async.cg.shared.global [%0], [%1], 16;"
                 :: "r"(sdst), "l"(gsrc));
}

union F4U2 { float4 f; ulonglong2 u; };

// =================================================================
// Kernel 1: h0[m,n] = scale[n] * sum_k x[m,k] * W[n,k]
// =================================================================
#define BM 64
#define BN 64
#define BK 16

__global__ __launch_bounds__(256) void gemm_k(const float* __restrict__ x,
                                              const float* __restrict__ W,
                                              const float* __restrict__ scale)
{
    __shared__ float As[BK][BM];
    __shared__ float Bs[BK][BN];

    const int m0  = blockIdx.y * BM;
    const int n0  = blockIdx.x * BN;
    const int tid = threadIdx.x;
    const int lrow = tid >> 2;
    const int lk   = (tid & 3) << 2;
    const int tx = tid & 15;
    const int ty = tid >> 4;

    float acc[4][4];
#pragma unroll
    for (int i = 0; i < 4; i++)
#pragma unroll
        for (int j = 0; j < 4; j++) acc[i][j] = 0.f;

    const float* xg = x + (size_t)(m0 + lrow) * D_;
    const float* wg = W + (size_t)(n0 + lrow) * D_;

    for (int k0 = 0; k0 < D_; k0 += BK) {
        float4 a = *(const float4*)(xg + k0 + lk);
        float4 b = *(const float4*)(wg + k0 + lk);
        __syncthreads();
        As[lk + 0][lrow] = a.x; As[lk + 1][lrow] = a.y;
        As[lk + 2][lrow] = a.z; As[lk + 3][lrow] = a.w;
        Bs[lk + 0][lrow] = b.x; Bs[lk + 1][lrow] = b.y;
        Bs[lk + 2][lrow] = b.z; Bs[lk + 3][lrow] = b.w;
        __syncthreads();
#pragma unroll
        for (int k = 0; k < BK; k++) {
            float4 av = *(const float4*)&As[k][ty << 2];
            float4 bv = *(const float4*)&Bs[k][tx << 2];
            acc[0][0] += av.x * bv.x; acc[0][1] += av.x * bv.y;
            acc[0][2] += av.x * bv.z; acc[0][3] += av.x * bv.w;
            acc[1][0] += av.y * bv.x; acc[1][1] += av.y * bv.y;
            acc[1][2] += av.y * bv.z; acc[1][3] += av.y * bv.w;
            acc[2][0] += av.z * bv.x; acc[2][1] += av.z * bv.y;
            acc[2][2] += av.z * bv.z; acc[2][3] += av.z * bv.w;
            acc[3][0] += av.w * bv.x; acc[3][1] += av.w * bv.y;
            acc[3][2] += av.w * bv.z; acc[3][3] += av.w * bv.w;
        }
    }

    const int nc = n0 + (tx << 2);
    float4 sc = *(const float4*)(scale + nc);
#pragma unroll
    for (int i = 0; i < 4; i++) {
        const int row = m0 + (ty << 2) + i;
        float4 o;
        o.x = acc[i][0] * sc.x; o.y = acc[i][1] * sc.y;
        o.z = acc[i][2] * sc.z; o.w = acc[i][3] * sc.w;
        *(float4*)&g_h0[(size_t)row * D_ + nc] = o;
    }
}

// =================================================================
// Kernel 2: per-feature mean / rstd
// =================================================================
__global__ __launch_bounds__(256) void stats_k()
{
    const int f = blockIdx.x;
    const int tid = threadIdx.x;
    float s = 0.f, s2 = 0.f;
    for (int r = tid; r < M_; r += 256) {
        float v = g_h0[(size_t)r * D_ + f];
        s += v; s2 += v * v;
    }
#pragma unroll
    for (int off = 16; off > 0; off >>= 1) {
        s  += __shfl_down_sync(0xffffffffu, s,  off);
        s2 += __shfl_down_sync(0xffffffffu, s2, off);
    }
    __shared__ float ws[8], ws2[8];
    if ((tid & 31) == 0) { ws[tid >> 5] = s; ws2[tid >> 5] = s2; }
    __syncthreads();
    if (tid == 0) {
        float S = 0.f, S2 = 0.f;
#pragma unroll
        for (int i = 0; i < 8; i++) { S += ws[i]; S2 += ws2[i]; }
        float mu  = S / (float)M_;
        float var = S2 / (float)M_ - mu * mu;
        g_mu[f]   = mu;
        g_rstd[f] = rsqrtf(var + EPS_);
    }
}

// =================================================================
// Kernel 3: BN affine + ReLU*mask + adds -> d_out
// =================================================================
__global__ __launch_bounds__(256) void apply_k(const float* __restrict__ gamma,
                                               const float* __restrict__ beta,
                                               const float* __restrict__ mask,
                                               const float* __restrict__ residual,
                                               const float* __restrict__ attention,
                                               const float* __restrict__ positional,
                                               float* __restrict__ out)
{
    const int n4 = (M_ * D_) / 4;
    for (int i = blockIdx.x * blockDim.x + threadIdx.x; i < n4;
         i += gridDim.x * blockDim.x) {
        const int f4 = i & (D_ / 4 - 1);
        float4 hv = ((const float4*)g_h0)[i];
        float4 g  = ((const float4*)gamma)[f4];
        float4 bt = ((const float4*)beta)[f4];
        float4 mu = ((const float4*)g_mu)[f4];
        float4 rs = ((const float4*)g_rstd)[f4];
        float4 mk = ((const float4*)mask)[i];
        float4 rd = ((const float4*)residual)[i];
        float4 at = ((const float4*)attention)[i];
        float4 ps = ((const float4*)positional)[i];
        float4 y;
        y.x = fmaxf(g.x * (hv.x - mu.x) * rs.x + bt.x, 0.f) * mk.x + rd.x + at.x + ps.x;
        y.y = fmaxf(g.y * (hv.y - mu.y) * rs.y + bt.y, 0.f) * mk.y + rd.y + at.y + ps.y;
        y.z = fmaxf(g.z * (hv.z - mu.z) * rs.z + bt.z, 0.f) * mk.z + rd.z + at.z + ps.z;
        y.w = fmaxf(g.w * (hv.w - mu.w) * rs.w + bt.w, 0.f) * mk.w + rd.w + at.w + ps.w;
        ((float4*)out)[i] = y;
    }
}

// =================================================================
// Kernel 4 (x6): flash-attention, lane-pair d-split.
// Each query row is owned by a LANE PAIR (even lane: 16B units
// 0,2,..,14 of the 64-float head slice; odd lane: units 1,3,..,15).
// Per-thread state halves vs one-thread-per-row -> ~110 regs ->
// 4 CTAs/SM. Partial scores combined with one shfl_xor(.,1);
// softmax state (m,l) computed identically on both lanes
// (fp32 add is commutative -> bitwise lock-step).
// In-place h update race-free (row pair writes disjoint units).
// =================================================================
#define QT2 64   // query rows per block (128 threads / 2 per row)
#define KT  32   // keys per smem tile
#define KH  8    // score batch

__global__ __launch_bounds__(128, 4) void flash_k(float* __restrict__ h,
                                                  const float* __restrict__ qb,
                                                  const float* __restrict__ kb,
                                                  const float* __restrict__ vb)
{
    // [buf][K=0/V=1][key][16B-unit]  : 2*2*32*16*16B = 32 KB
    __shared__ F4U2 KVs[2][2][KT][DH_ / 4];

    const int tid = threadIdx.x;
    const int par = tid & 1;             // which unit parity this lane owns
    const int row = tid >> 1;            // 0..63
    const int sq  = blockIdx.x * QT2 + row;
    const int hh  = blockIdx.y;
    const int b   = blockIdx.z;
    const size_t rowoff  = ((size_t)(b * S_ + sq)) * D_ + hh * DH_;
    const size_t headoff = ((size_t)b * S_) * D_ + hh * DH_;

    // 8 16B-units -> 16 packed f32x2 regs for q and o
    ull q2[16], o2[16];
    {
        const F4U2* hrow = (const F4U2*)(h + rowoff);
        const F4U2* qrow = (const F4U2*)(qb + rowoff);
#pragma unroll
        for (int i = 0; i < 8; i++) {
            const int u = par + 2 * i;
            F4U2 a = hrow[u], c = qrow[u];
            q2[2 * i]     = d_add2(a.u.x, c.u.x);
            q2[2 * i + 1] = d_add2(a.u.y, c.u.y);
            o2[2 * i]     = 0ull;
            o2[2 * i + 1] = 0ull;
        }
    }
    float m = -1e30f, l = 0.f;

    // loader: 1024 16B units per tile (K:512, V:512), 8 per thread
    auto load_tile = [&](int kt, int bf) {
#pragma unroll
        for (int li = 0; li < 8; li++) {
            int idx = tid + li * 128;          // 0..1023
            int kv  = idx >> 9;                // 0:K 1:V
            int j   = (idx >> 4) & 31;
            int u   = idx & 15;
            const float* gsrc = (kv ? vb : kb) + headoff
                              + (size_t)(kt + j) * D_ + u * 4;
            cp16((unsigned int)__cvta_generic_to_shared(&KVs[bf][kv][j][u]), gsrc);
        }
        asm volatile("cp.async.commit_group;" ::: "memory");
    };

    load_tile(0, 0);

    for (int kt = 0, t = 0; kt < S_; kt += KT, t++) {
        asm volatile("cp.async.wait_group 0;" ::: "memory");
        __syncthreads();
        if (kt + KT < S_) load_tile(kt + KT, (t + 1) & 1);
        const int bf = t & 1;
        const F4U2 (*Ks)[DH_ / 4] = KVs[bf][0];
        const F4U2 (*Vs)[DH_ / 4] = KVs[bf][1];

#pragma unroll
        for (int batch = 0; batch < KT / KH; batch++) {
            const int jb = batch * KH;
            float p[KH];
            // partial scores over this lane's 8 units
#pragma unroll
            for (int j = 0; j < KH; j++) {
                ull a0 = 0ull, a1 = 0ull, a2 = 0ull, a3 = 0ull;
                const F4U2* kr = Ks[jb + j];
#pragma unroll
                for (int i = 0; i < 8; i += 2) {
                    F4U2 k0 = kr[par + 2 * i];
                    F4U2 k1 = kr[par + 2 * (i + 1)];
                    a0 = d_fma2(q2[2 * i],     k0.u.x, a0);
                    a1 = d_fma2(q2[2 * i + 1], k0.u.y, a1);
                    a2 = d_fma2(q2[2 * i + 2], k1.u.x, a2);
                    a3 = d_fma2(q2[2 * i + 3], k1.u.y, a3);
                }
                a0 = d_add2(a0, a2);
                a1 = d_add2(a1, a3);
                a0 = d_add2(a0, a1);
                float2 sf = unpack2(a0);
                p[j] = sf.x + sf.y;
            }
            // combine lane-pair partials (independent shuffles, pipelined)
            float mnew = m;
#pragma unroll
            for (int j = 0; j < KH; j++) {
                p[j] = (p[j] + __shfl_xor_sync(0xffffffffu, p[j], 1)) * 0.125f;
                mnew = fmaxf(mnew, p[j]);
            }
            float corr = __expf(m - mnew);
            m = mnew;
            l *= corr;
            {
                ull cc = pack2(corr, corr);
#pragma unroll
                for (int i = 0; i < 16; i++) o2[i] = d_mul2(o2[i], cc);
            }
#pragma unroll
            for (int j = 0; j < KH; j++) {
                float pj = __expf(p[j] - m);
                l += pj;
                ull pp = pack2(pj, pj);
                const F4U2* vr = Vs[jb + j];
#pragma unroll
                for (int i = 0; i < 8; i++) {
                    F4U2 vv = vr[par + 2 * i];
                    o2[2 * i]     = d_fma2(pp, vv.u.x, o2[2 * i]);
                    o2[2 * i + 1] = d_fma2(pp, vv.u.y, o2[2 * i + 1]);
                }
            }
        }
    }

    const float inv = 1.f / l;
    F4U2* hw = (F4U2*)(h + rowoff);
#pragma unroll
    for (int i = 0; i < 8; i++) {
        const int u = par + 2 * i;
        F4U2 a = hw[u];
        float2 e0 = unpack2(o2[2 * i]);
        float2 e1 = unpack2(o2[2 * i + 1]);
        a.f.x += e0.x * inv; a.f.y += e0.y * inv;
        a.f.z += e1.x * inv; a.f.w += e1.y * inv;
        hw[u] = a;
    }
}

// =================================================================
// launch
// =================================================================
extern "C" void kernel_launch(void* const* d_in, const int* in_sizes, int n_in,
                              void* d_out, int out_size)
{
    const float* x          = (const float*)d_in[0];
    const float* W          = (const float*)d_in[1];
    const float* scale      = (const float*)d_in[2];
    const float* gamma      = (const float*)d_in[3];
    const float* beta       = (const float*)d_in[4];
    const float* mask       = (const float*)d_in[5];
    const float* residual   = (const float*)d_in[6];
    const float* attention  = (const float*)d_in[7];
    const float* positional = (const float*)d_in[8];
    float* out = (float*)d_out;

    dim3 gg(D_ / BN, M_ / BM);
    gemm_k<<<gg, 256>>>(x, W, scale);

    stats_k<<<D_, 256>>>();

    apply_k<<<2048, 256>>>(gamma, beta, mask, residual, attention, positional, out);

    dim3 fg(S_ / QT2, H_, B_);              // (16, 16, 4) = 1024 blocks
    for (int t = 0; t < 6; t++) {
        flash_k<<<fg, 128>>>(out,
                             (const float*)d_in[9  + 3 * t],
                             (const float*)d_in[10 + 3 * t],
                             (const float*)d_in[11 + 3 * t]);
    }
}